// round 1
// baseline (speedup 1.0000x reference)
#include <cuda_runtime.h>
#include <cstdint>

// ---------------------------------------------------------------------------
// GraphFormer encoder layer, fp32 baseline.
// B=4, T=1024, D=1024, H=16, DH=64, F=4096.  M = B*T = 4096.
// Output: [ x (4M floats) | attn (64M floats, (B,H,T,S)) ]
// ---------------------------------------------------------------------------

#define Bq 4
#define Tq 1024
#define Dq 1024
#define Hq 16
#define DHq 64
#define Fq 4096
#define Mq (Bq*Tq)              // 4096
#define XSZ (Mq*Dq)             // 4194304

// Scratch (static device globals -- allocation is forbidden)
__device__ float g_xn [XSZ];    // ln1 output (= residual)
__device__ float g_q  [XSZ];
__device__ float g_k  [XSZ];    // kb = k + spatial + edge (fused)
__device__ float g_v  [XSZ];
__device__ float g_ctx[XSZ];
__device__ float g_t1 [XSZ];    // ctx @ Wo + bo
__device__ float g_x2 [XSZ];    // ln2 output
__device__ float g_h  [Mq*Fq];  // FFN hidden (gelu)
__device__ float g_t2 [XSZ];    // h @ W2 + b2

__device__ __forceinline__ float gelu_tanh(float x) {
    // jax.nn.gelu default (approximate=True)
    float x3 = x * x * x;
    return 0.5f * x * (1.0f + tanhf(0.7978845608028654f * (x + 0.044715f * x3)));
}

// ---------------------------------------------------------------------------
// LayerNorm over D=1024, one block (256 thr) per row. Optional residual add.
// ---------------------------------------------------------------------------
__global__ void ln_kernel(const float* __restrict__ in, const float* __restrict__ res,
                          const float* __restrict__ gamma, const float* __restrict__ beta,
                          float* __restrict__ out) {
    int row = blockIdx.x;
    int tid = threadIdx.x;
    const float* ir = in + (size_t)row * Dq;
    const float* rr = res ? res + (size_t)row * Dq : nullptr;

    float vals[4];
    float s = 0.f, sq = 0.f;
#pragma unroll
    for (int i = 0; i < 4; i++) {
        int c = tid + i * 256;
        float v = ir[c];
        if (rr) v += rr[c];
        vals[i] = v;
        s += v; sq += v * v;
    }
    // block reduce (sum, sumsq)
    __shared__ float ss[8], ssq[8];
    int lane = tid & 31, wid = tid >> 5;
#pragma unroll
    for (int o = 16; o > 0; o >>= 1) {
        s  += __shfl_down_sync(0xffffffffu, s,  o);
        sq += __shfl_down_sync(0xffffffffu, sq, o);
    }
    if (lane == 0) { ss[wid] = s; ssq[wid] = sq; }
    __syncthreads();
    if (wid == 0) {
        s  = (lane < 8) ? ss[lane]  : 0.f;
        sq = (lane < 8) ? ssq[lane] : 0.f;
#pragma unroll
        for (int o = 4; o > 0; o >>= 1) {
            s  += __shfl_down_sync(0xffffffffu, s,  o);
            sq += __shfl_down_sync(0xffffffffu, sq, o);
        }
        if (lane == 0) { ss[0] = s; ssq[0] = sq; }
    }
    __syncthreads();
    float mean = ss[0] * (1.0f / Dq);
    float var  = ssq[0] * (1.0f / Dq) - mean * mean;
    float inv  = rsqrtf(var + 1e-5f);

    float* orow = out + (size_t)row * Dq;
#pragma unroll
    for (int i = 0; i < 4; i++) {
        int c = tid + i * 256;
        orow[c] = (vals[i] - mean) * inv * gamma[c] + beta[c];
    }
}

// ---------------------------------------------------------------------------
// SGEMM NN: C[M,N] = A[M,K] @ Bm[K,N] + bias[N]  (+ e1 + e2 elementwise)
// act: 0 = none, 1 = gelu.  128x128 tile, BK=8, 256 threads, 8x8 per thread.
// M,N % 128 == 0, K % 8 == 0.
// ---------------------------------------------------------------------------
__global__ __launch_bounds__(256, 2)
void sgemm_nn(const float* __restrict__ A, const float* __restrict__ Bm,
              const float* __restrict__ bias, float* __restrict__ C,
              int M, int N, int K,
              const float* __restrict__ e1, const float* __restrict__ e2,
              int act) {
    __shared__ float As[8][128];
    __shared__ float Bs[8][128];

    int bm = blockIdx.y * 128;
    int bn = blockIdx.x * 128;
    int tid = threadIdx.x;

    int arow = tid >> 1;           // 0..127
    int acol = (tid & 1) * 4;      // 0 or 4
    int brow = tid >> 5;           // 0..7
    int bcol = (tid & 31) * 4;     // 0..124
    int tx = tid & 15, ty = tid >> 4;

    float acc[8][8] = {};

    for (int k0 = 0; k0 < K; k0 += 8) {
        float4 av = *(const float4*)(A + (size_t)(bm + arow) * K + k0 + acol);
        As[acol + 0][arow] = av.x;
        As[acol + 1][arow] = av.y;
        As[acol + 2][arow] = av.z;
        As[acol + 3][arow] = av.w;
        float4 bv = *(const float4*)(Bm + (size_t)(k0 + brow) * N + bn + bcol);
        *(float4*)&Bs[brow][bcol] = bv;
        __syncthreads();
#pragma unroll
        for (int kk = 0; kk < 8; kk++) {
            float4 a0 = *(const float4*)&As[kk][ty * 8];
            float4 a1 = *(const float4*)&As[kk][ty * 8 + 4];
            float4 b0 = *(const float4*)&Bs[kk][tx * 8];
            float4 b1 = *(const float4*)&Bs[kk][tx * 8 + 4];
            float ar[8] = {a0.x, a0.y, a0.z, a0.w, a1.x, a1.y, a1.z, a1.w};
            float br[8] = {b0.x, b0.y, b0.z, b0.w, b1.x, b1.y, b1.z, b1.w};
#pragma unroll
            for (int i = 0; i < 8; i++)
#pragma unroll
                for (int j = 0; j < 8; j++)
                    acc[i][j] += ar[i] * br[j];
        }
        __syncthreads();
    }

#pragma unroll
    for (int i = 0; i < 8; i++) {
        int row = bm + ty * 8 + i;
        size_t base = (size_t)row * N;
#pragma unroll
        for (int j4 = 0; j4 < 2; j4++) {
            int col = bn + tx * 8 + j4 * 4;
            float4 bb = *(const float4*)(bias + col);
            float4 c;
            c.x = acc[i][j4 * 4 + 0] + bb.x;
            c.y = acc[i][j4 * 4 + 1] + bb.y;
            c.z = acc[i][j4 * 4 + 2] + bb.z;
            c.w = acc[i][j4 * 4 + 3] + bb.w;
            if (e1) {
                float4 a1 = *(const float4*)(e1 + base + col);
                float4 a2 = *(const float4*)(e2 + base + col);
                c.x += a1.x + a2.x; c.y += a1.y + a2.y;
                c.z += a1.z + a2.z; c.w += a1.w + a2.w;
            }
            if (act == 1) {
                c.x = gelu_tanh(c.x); c.y = gelu_tanh(c.y);
                c.z = gelu_tanh(c.z); c.w = gelu_tanh(c.w);
            }
            *(float4*)(C + base + col) = c;
        }
    }
}

// ---------------------------------------------------------------------------
// scores: S[bh][t][s] = 0.125 * sum_d q[b,t,h,d] * kb[b,s,h,d]
// 64x64 tile per block, K=64 fully resident. grid (16,16,64), 256 threads.
// ---------------------------------------------------------------------------
__global__ __launch_bounds__(256)
void scores_kernel(const float* __restrict__ q, const float* __restrict__ kb,
                   float* __restrict__ attn) {
    int bh = blockIdx.z;
    int b = bh >> 4, h = bh & 15;
    const float* Q  = q  + (size_t)b * Tq * Dq + h * DHq;
    const float* KB = kb + (size_t)b * Tq * Dq + h * DHq;
    float* S = attn + (size_t)bh * Tq * Tq;

    int t0 = blockIdx.y * 64, s0 = blockIdx.x * 64;

    __shared__ float Qs[64][65];   // [d][t], padded
    __shared__ float Ks[64][65];   // [d][s]

    int tid = threadIdx.x;
    int lr = tid >> 4;             // 0..15
    int lc = (tid & 15) * 4;       // 0..60
#pragma unroll
    for (int r = 0; r < 4; r++) {
        int row = lr + r * 16;
        float4 qv = *(const float4*)(Q + (size_t)(t0 + row) * Dq + lc);
        Qs[lc + 0][row] = qv.x; Qs[lc + 1][row] = qv.y;
        Qs[lc + 2][row] = qv.z; Qs[lc + 3][row] = qv.w;
        float4 kv = *(const float4*)(KB + (size_t)(s0 + row) * Dq + lc);
        Ks[lc + 0][row] = kv.x; Ks[lc + 1][row] = kv.y;
        Ks[lc + 2][row] = kv.z; Ks[lc + 3][row] = kv.w;
    }
    __syncthreads();

    int tx = tid & 15, ty = tid >> 4;
    float acc[4][4] = {};
#pragma unroll 16
    for (int d = 0; d < 64; d++) {
        float a[4], bv[4];
#pragma unroll
        for (int i = 0; i < 4; i++) a[i]  = Qs[d][ty * 4 + i];
#pragma unroll
        for (int j = 0; j < 4; j++) bv[j] = Ks[d][tx * 4 + j];
#pragma unroll
        for (int i = 0; i < 4; i++)
#pragma unroll
            for (int j = 0; j < 4; j++)
                acc[i][j] += a[i] * bv[j];
    }

#pragma unroll
    for (int i = 0; i < 4; i++) {
        size_t base = (size_t)(t0 + ty * 4 + i) * Tq + s0 + tx * 4;
        float4 c;
        c.x = acc[i][0] * 0.125f; c.y = acc[i][1] * 0.125f;
        c.z = acc[i][2] * 0.125f; c.w = acc[i][3] * 0.125f;
        *(float4*)(S + base) = c;
    }
}

// ---------------------------------------------------------------------------
// softmax in-place over last dim (1024). One block per row.
// ---------------------------------------------------------------------------
__global__ void softmax_kernel(float* __restrict__ attn) {
    size_t row = blockIdx.x;
    float* r = attn + row * Tq;
    int tid = threadIdx.x;
    int lane = tid & 31, wid = tid >> 5;
    __shared__ float sred[8];

    float v[4];
    float mx = -1e30f;
#pragma unroll
    for (int i = 0; i < 4; i++) { v[i] = r[tid + i * 256]; mx = fmaxf(mx, v[i]); }
#pragma unroll
    for (int o = 16; o > 0; o >>= 1) mx = fmaxf(mx, __shfl_down_sync(0xffffffffu, mx, o));
    if (lane == 0) sred[wid] = mx;
    __syncthreads();
    if (wid == 0) {
        mx = (lane < 8) ? sred[lane] : -1e30f;
#pragma unroll
        for (int o = 4; o > 0; o >>= 1) mx = fmaxf(mx, __shfl_down_sync(0xffffffffu, mx, o));
        if (lane == 0) sred[0] = mx;
    }
    __syncthreads();
    mx = sred[0];
    __syncthreads();

    float s = 0.f;
#pragma unroll
    for (int i = 0; i < 4; i++) { v[i] = __expf(v[i] - mx); s += v[i]; }
#pragma unroll
    for (int o = 16; o > 0; o >>= 1) s += __shfl_down_sync(0xffffffffu, s, o);
    if (lane == 0) sred[wid] = s;
    __syncthreads();
    if (wid == 0) {
        s = (lane < 8) ? sred[lane] : 0.f;
#pragma unroll
        for (int o = 4; o > 0; o >>= 1) s += __shfl_down_sync(0xffffffffu, s, o);
        if (lane == 0) sred[0] = s;
    }
    __syncthreads();
    float inv = 1.0f / sred[0];
#pragma unroll
    for (int i = 0; i < 4; i++) r[tid + i * 256] = v[i] * inv;
}

// ---------------------------------------------------------------------------
// attn @ v : ctx[b,t,h,:] = sum_s attn[bh][t][s] * v[b,s,h,:]
// 64(t) x 64(dh) tile per block, BK=16. grid (16, 64), 256 threads.
// ---------------------------------------------------------------------------
__global__ __launch_bounds__(256)
void av_kernel(const float* __restrict__ attn, const float* __restrict__ v,
               float* __restrict__ ctx) {
    int bh = blockIdx.y;
    int b = bh >> 4, h = bh & 15;
    const float* A = attn + (size_t)bh * Tq * Tq;
    const float* V = v   + (size_t)b * Tq * Dq + h * DHq;
    float* C       = ctx + (size_t)b * Tq * Dq + h * DHq;
    int t0 = blockIdx.x * 64;

    __shared__ float As[16][65];   // [s'][t], padded
    __shared__ float Vs[16][64];   // [s'][dh]

    int tid = threadIdx.x;
    int tx = tid & 15, ty = tid >> 4;
    int ar = tid >> 2;             // 0..63 (t within tile)
    int ac = (tid & 3) * 4;        // 0..12 (s within 16)
    int vr = tid >> 4;             // 0..15 (s within 16)
    int vc = (tid & 15) * 4;       // 0..60 (dh)

    float acc[4][4] = {};
    for (int s0 = 0; s0 < Tq; s0 += 16) {
        float4 av = *(const float4*)(A + (size_t)(t0 + ar) * Tq + s0 + ac);
        As[ac + 0][ar] = av.x; As[ac + 1][ar] = av.y;
        As[ac + 2][ar] = av.z; As[ac + 3][ar] = av.w;
        float4 vv = *(const float4*)(V + (size_t)(s0 + vr) * Dq + vc);
        *(float4*)&Vs[vr][vc] = vv;
        __syncthreads();
#pragma unroll
        for (int kk = 0; kk < 16; kk++) {
            float a[4], bv[4];
#pragma unroll
            for (int i = 0; i < 4; i++) a[i]  = As[kk][ty * 4 + i];
#pragma unroll
            for (int j = 0; j < 4; j++) bv[j] = Vs[kk][tx * 4 + j];
#pragma unroll
            for (int i = 0; i < 4; i++)
#pragma unroll
                for (int j = 0; j < 4; j++)
                    acc[i][j] += a[i] * bv[j];
        }
        __syncthreads();
    }
#pragma unroll
    for (int i = 0; i < 4; i++) {
        size_t base = (size_t)(t0 + ty * 4 + i) * Dq + tx * 4;
        float4 c = {acc[i][0], acc[i][1], acc[i][2], acc[i][3]};
        *(float4*)(C + base) = c;
    }
}

// ---------------------------------------------------------------------------
extern "C" void kernel_launch(void* const* d_in, const int* in_sizes, int n_in,
                              void* d_out, int out_size) {
    const float* x     = (const float*)d_in[0];
    const float* sp    = (const float*)d_in[1];
    const float* ed    = (const float*)d_in[2];
    const float* ln1_g = (const float*)d_in[3];
    const float* ln1_b = (const float*)d_in[4];
    const float* Wq    = (const float*)d_in[5];
    const float* bq    = (const float*)d_in[6];
    const float* Wk    = (const float*)d_in[7];
    const float* bk    = (const float*)d_in[8];
    const float* Wv    = (const float*)d_in[9];
    const float* bv    = (const float*)d_in[10];
    const float* Wo    = (const float*)d_in[11];
    const float* bo    = (const float*)d_in[12];
    const float* ln2_g = (const float*)d_in[13];
    const float* ln2_b = (const float*)d_in[14];
    const float* W1    = (const float*)d_in[15];
    const float* b1    = (const float*)d_in[16];
    const float* W2    = (const float*)d_in[17];
    const float* b2    = (const float*)d_in[18];
    const float* lnb_g = (const float*)d_in[19];
    const float* lnb_b = (const float*)d_in[20];

    float* out_x = (float*)d_out;
    float* attn  = out_x + (size_t)XSZ;   // (B,H,T,S) region of d_out

    float *xn, *q, *k, *v, *ctx, *t1, *x2, *hb, *t2;
    cudaGetSymbolAddress((void**)&xn,  g_xn);
    cudaGetSymbolAddress((void**)&q,   g_q);
    cudaGetSymbolAddress((void**)&k,   g_k);
    cudaGetSymbolAddress((void**)&v,   g_v);
    cudaGetSymbolAddress((void**)&ctx, g_ctx);
    cudaGetSymbolAddress((void**)&t1,  g_t1);
    cudaGetSymbolAddress((void**)&x2,  g_x2);
    cudaGetSymbolAddress((void**)&hb,  g_h);
    cudaGetSymbolAddress((void**)&t2,  g_t2);

    // 1) ln1
    ln_kernel<<<Mq, 256>>>(x, nullptr, ln1_g, ln1_b, xn);

    // 2) Q/K/V projections (K fuses +spatial+edge -> kb)
    sgemm_nn<<<dim3(Dq / 128, Mq / 128), 256>>>(xn, Wq, bq, q, Mq, Dq, Dq, nullptr, nullptr, 0);
    sgemm_nn<<<dim3(Dq / 128, Mq / 128), 256>>>(xn, Wk, bk, k, Mq, Dq, Dq, sp, ed, 0);
    sgemm_nn<<<dim3(Dq / 128, Mq / 128), 256>>>(xn, Wv, bv, v, Mq, Dq, Dq, nullptr, nullptr, 0);

    // 3) attention scores -> softmax (in-place in d_out) -> attn @ v
    scores_kernel<<<dim3(16, 16, Bq * Hq), 256>>>(q, k, attn);
    softmax_kernel<<<Bq * Hq * Tq, 256>>>(attn);
    av_kernel<<<dim3(16, Bq * Hq), 256>>>(attn, v, ctx);

    // 4) output projection + residual + ln2
    sgemm_nn<<<dim3(Dq / 128, Mq / 128), 256>>>(ctx, Wo, bo, t1, Mq, Dq, Dq, nullptr, nullptr, 0);
    ln_kernel<<<Mq, 256>>>(t1, xn, ln2_g, ln2_b, x2);

    // 5) FFN + residual + final ln -> d_out
    sgemm_nn<<<dim3(Fq / 128, Mq / 128), 256>>>(x2, W1, b1, hb, Mq, Fq, Dq, nullptr, nullptr, 1);
    sgemm_nn<<<dim3(Dq / 128, Mq / 128), 256>>>(hb, W2, b2, t2, Mq, Dq, Fq, nullptr, nullptr, 0);
    ln_kernel<<<Mq, 256>>>(t2, x2, lnb_g, lnb_b, out_x);
}

// round 3
// speedup vs baseline: 1.8836x; 1.8836x over previous
#include <cuda_runtime.h>
#include <cstdint>

// ---------------------------------------------------------------------------
// GraphFormer encoder layer. mma.sync tf32 GEMMs + fp32 SIMT attention.
// B=4, T=1024, D=1024, H=16, DH=64, F=4096.  M = B*T = 4096.
// Output: [ x (4M floats) | attn (64M floats, (B,H,T,S)) ]
// ---------------------------------------------------------------------------

#define Bq 4
#define Tq 1024
#define Dq 1024
#define Hq 16
#define DHq 64
#define Fq 4096
#define Mq (Bq*Tq)              // 4096
#define XSZ (Mq*Dq)             // 4194304

// Scratch (static device globals -- allocation is forbidden)
__device__ float g_xn [XSZ];    // ln1 output (= residual)
__device__ float g_q  [XSZ];
__device__ float g_k  [XSZ];    // kb = k + spatial + edge (fused)
__device__ float g_v  [XSZ];
__device__ float g_ctx[XSZ];
__device__ float g_t1 [XSZ];    // ctx @ Wo + bo
__device__ float g_x2 [XSZ];    // ln2 output
__device__ float g_h  [Mq*Fq];  // FFN hidden (gelu)
__device__ float g_t2 [XSZ];    // h @ W2 + b2

__device__ __forceinline__ float gelu_tanh(float x) {
    float x3 = x * x * x;
    return 0.5f * x * (1.0f + tanhf(0.7978845608028654f * (x + 0.044715f * x3)));
}

__device__ __forceinline__ uint32_t smem_u32(const void* p) {
    uint32_t a;
    asm("{ .reg .u64 t; cvta.to.shared.u64 t, %1; cvt.u32.u64 %0, t; }"
        : "=r"(a) : "l"(p));
    return a;
}
__device__ __forceinline__ uint32_t f2tf32(float v) {
    uint32_t t;
    asm("cvt.rna.tf32.f32 %0, %1;" : "=r"(t) : "f"(v));
    return t;
}
__device__ __forceinline__ void cp16(uint32_t dst, const void* src) {
    asm volatile("cp.async.cg.shared.global [%0], [%1], 16;" :: "r"(dst), "l"(src));
}
__device__ __forceinline__ void cp_commit() {
    asm volatile("cp.async.commit_group;" ::: "memory");
}
__device__ __forceinline__ void cp_wait0() {
    asm volatile("cp.async.wait_group 0;" ::: "memory");
}
__device__ __forceinline__ void mma_tf32(float& c0, float& c1, float& c2, float& c3,
                                         uint32_t a0, uint32_t a1, uint32_t a2, uint32_t a3,
                                         uint32_t b0, uint32_t b1) {
    asm volatile("mma.sync.aligned.m16n8k8.row.col.f32.tf32.tf32.f32 "
                 "{%0,%1,%2,%3}, {%4,%5,%6,%7}, {%8,%9}, {%0,%1,%2,%3};"
                 : "+f"(c0), "+f"(c1), "+f"(c2), "+f"(c3)
                 : "r"(a0), "r"(a1), "r"(a2), "r"(a3), "r"(b0), "r"(b1));
}

// ---------------------------------------------------------------------------
// mma.sync tf32 GEMM: C[M,N] = A[M,K] @ Bm[K,N] + bias (+e1+e2 | gelu)
// 128x128 tile, BK=16, 256 thr = 8 warps (2x4), warp tile 64x32.
// ---------------------------------------------------------------------------
#define ASTR 20
#define BSTR 132

__global__ __launch_bounds__(256)
void gemm_mma(const float* __restrict__ A, const float* __restrict__ Bm,
              const float* __restrict__ bias, float* __restrict__ C,
              int K, int N,
              const float* __restrict__ e1, const float* __restrict__ e2, int act) {
    __shared__ __align__(16) float As[2][128 * ASTR];
    __shared__ __align__(16) float Bs[2][16 * BSTR];

    const int tid = threadIdx.x;
    const int wid = tid >> 5, lane = tid & 31;
    const int g = lane >> 2, tig = lane & 3;       // group / thread-in-group
    const int wm = (wid >> 2) * 64;                // warp row offset (0/64)
    const int wn = (wid & 3) * 32;                 // warp col offset (0..96)
    const int bm = blockIdx.y * 128, bn = blockIdx.x * 128;

    // cp.async source/dest mapping
    const int arow = tid >> 1, acol = (tid & 1) * 8;   // A: 128 rows x 16 cols
    const int brow = tid >> 4, bcol = (tid & 15) * 8;  // B: 16 rows x 128 cols
    const float* Agp = A + (size_t)(bm + arow) * K + acol;
    const float* Bgp = Bm + (size_t)brow * N + bn + bcol;

    const uint32_t sA = smem_u32(As), sB = smem_u32(Bs);
    const uint32_t aDst = sA + (arow * ASTR + acol) * 4;
    const uint32_t bDst = sB + (brow * BSTR + bcol) * 4;

    float acc[4][4][4] = {};   // [mi][nj][c0..c3]

    const int NIT = K >> 4;

    // prologue: stage 0
    cp16(aDst, Agp);           cp16(aDst + 16, Agp + 4);
    cp16(bDst, Bgp);           cp16(bDst + 16, Bgp + 4);
    cp_commit();

    for (int it = 0; it < NIT; it++) {
        const int cur = it & 1;
        cp_wait0();
        __syncthreads();
        if (it + 1 < NIT) {
            const int nxt = 1 - cur;
            const float* ag = Agp + (size_t)(it + 1) * 16;
            const float* bg = Bgp + (size_t)(it + 1) * 16 * N;
            const uint32_t ad = aDst + nxt * (128 * ASTR * 4);
            const uint32_t bd = bDst + nxt * (16 * BSTR * 4);
            cp16(ad, ag);       cp16(ad + 16, ag + 4);
            cp16(bd, bg);       cp16(bd + 16, bg + 4);
            cp_commit();
        }

        const float* as = As[cur];
        const float* bs = Bs[cur];
#pragma unroll
        for (int kg = 0; kg < 2; kg++) {
            const int k8 = kg * 8;
            uint32_t af[4][4], bf[4][2];
#pragma unroll
            for (int i = 0; i < 4; i++) {
                const float* ar = as + (wm + i * 16 + g) * ASTR + k8 + tig;
                af[i][0] = f2tf32(ar[0]);
                af[i][1] = f2tf32(ar[8 * ASTR]);
                af[i][2] = f2tf32(ar[4]);
                af[i][3] = f2tf32(ar[8 * ASTR + 4]);
            }
#pragma unroll
            for (int j = 0; j < 4; j++) {
                const float* br = bs + (k8 + tig) * BSTR + wn + j * 8 + g;
                bf[j][0] = f2tf32(br[0]);
                bf[j][1] = f2tf32(br[4 * BSTR]);
            }
#pragma unroll
            for (int i = 0; i < 4; i++)
#pragma unroll
                for (int j = 0; j < 4; j++)
                    mma_tf32(acc[i][j][0], acc[i][j][1], acc[i][j][2], acc[i][j][3],
                             af[i][0], af[i][1], af[i][2], af[i][3],
                             bf[j][0], bf[j][1]);
        }
        __syncthreads();
    }

    // ---- epilogue ----
#pragma unroll
    for (int i = 0; i < 4; i++) {
#pragma unroll
        for (int j = 0; j < 4; j++) {
            const int col = bn + wn + j * 8 + 2 * tig;
            const int r0 = bm + wm + i * 16 + g;
#pragma unroll
            for (int h = 0; h < 2; h++) {           // h=0: rows g, h=1: rows g+8
                const int row = r0 + h * 8;
                const size_t off = (size_t)row * N + col;
                float2 o;
                o.x = acc[i][j][h * 2 + 0];
                o.y = acc[i][j][h * 2 + 1];
                float2 bb = *(const float2*)(bias + col);
                o.x += bb.x; o.y += bb.y;
                if (e1) {
                    float2 a1 = *(const float2*)(e1 + off);
                    float2 a2 = *(const float2*)(e2 + off);
                    o.x += a1.x + a2.x; o.y += a1.y + a2.y;
                }
                if (act) { o.x = gelu_tanh(o.x); o.y = gelu_tanh(o.y); }
                *(float2*)(C + off) = o;
            }
        }
    }
}

// ---------------------------------------------------------------------------
// LayerNorm over D=1024, one block (256 thr) per row. Optional residual add.
// ---------------------------------------------------------------------------
__global__ void ln_kernel(const float* __restrict__ in, const float* __restrict__ res,
                          const float* __restrict__ gamma, const float* __restrict__ beta,
                          float* __restrict__ out) {
    int row = blockIdx.x;
    int tid = threadIdx.x;
    const float* ir = in + (size_t)row * Dq;
    const float* rr = res ? res + (size_t)row * Dq : nullptr;

    float vals[4];
    float s = 0.f, sq = 0.f;
#pragma unroll
    for (int i = 0; i < 4; i++) {
        int c = tid + i * 256;
        float v = ir[c];
        if (rr) v += rr[c];
        vals[i] = v;
        s += v; sq += v * v;
    }
    __shared__ float ss[8], ssq[8];
    int lane = tid & 31, wid = tid >> 5;
#pragma unroll
    for (int o = 16; o > 0; o >>= 1) {
        s  += __shfl_down_sync(0xffffffffu, s,  o);
        sq += __shfl_down_sync(0xffffffffu, sq, o);
    }
    if (lane == 0) { ss[wid] = s; ssq[wid] = sq; }
    __syncthreads();
    if (wid == 0) {
        s  = (lane < 8) ? ss[lane]  : 0.f;
        sq = (lane < 8) ? ssq[lane] : 0.f;
#pragma unroll
        for (int o = 4; o > 0; o >>= 1) {
            s  += __shfl_down_sync(0xffffffffu, s,  o);
            sq += __shfl_down_sync(0xffffffffu, sq, o);
        }
        if (lane == 0) { ss[0] = s; ssq[0] = sq; }
    }
    __syncthreads();
    float mean = ss[0] * (1.0f / Dq);
    float var  = ssq[0] * (1.0f / Dq) - mean * mean;
    float inv  = rsqrtf(var + 1e-5f);

    float* orow = out + (size_t)row * Dq;
#pragma unroll
    for (int i = 0; i < 4; i++) {
        int c = tid + i * 256;
        orow[c] = (vals[i] - mean) * inv * gamma[c] + beta[c];
    }
}

// ---------------------------------------------------------------------------
// scores: S[bh][t][s] = 0.125 * sum_d q[b,t,h,d] * kb[b,s,h,d]
// ---------------------------------------------------------------------------
__global__ __launch_bounds__(256)
void scores_kernel(const float* __restrict__ q, const float* __restrict__ kb,
                   float* __restrict__ attn) {
    int bh = blockIdx.z;
    int b = bh >> 4, h = bh & 15;
    const float* Q  = q  + (size_t)b * Tq * Dq + h * DHq;
    const float* KB = kb + (size_t)b * Tq * Dq + h * DHq;
    float* S = attn + (size_t)bh * Tq * Tq;

    int t0 = blockIdx.y * 64, s0 = blockIdx.x * 64;

    __shared__ float Qs[64][65];
    __shared__ float Ks[64][65];

    int tid = threadIdx.x;
    int lr = tid >> 4;
    int lc = (tid & 15) * 4;
#pragma unroll
    for (int r = 0; r < 4; r++) {
        int row = lr + r * 16;
        float4 qv = *(const float4*)(Q + (size_t)(t0 + row) * Dq + lc);
        Qs[lc + 0][row] = qv.x; Qs[lc + 1][row] = qv.y;
        Qs[lc + 2][row] = qv.z; Qs[lc + 3][row] = qv.w;
        float4 kv = *(const float4*)(KB + (size_t)(s0 + row) * Dq + lc);
        Ks[lc + 0][row] = kv.x; Ks[lc + 1][row] = kv.y;
        Ks[lc + 2][row] = kv.z; Ks[lc + 3][row] = kv.w;
    }
    __syncthreads();

    int tx = tid & 15, ty = tid >> 4;
    float acc[4][4] = {};
#pragma unroll 16
    for (int d = 0; d < 64; d++) {
        float a[4], bv[4];
#pragma unroll
        for (int i = 0; i < 4; i++) a[i]  = Qs[d][ty * 4 + i];
#pragma unroll
        for (int j = 0; j < 4; j++) bv[j] = Ks[d][tx * 4 + j];
#pragma unroll
        for (int i = 0; i < 4; i++)
#pragma unroll
            for (int j = 0; j < 4; j++)
                acc[i][j] += a[i] * bv[j];
    }

#pragma unroll
    for (int i = 0; i < 4; i++) {
        size_t base = (size_t)(t0 + ty * 4 + i) * Tq + s0 + tx * 4;
        float4 c;
        c.x = acc[i][0] * 0.125f; c.y = acc[i][1] * 0.125f;
        c.z = acc[i][2] * 0.125f; c.w = acc[i][3] * 0.125f;
        *(float4*)(S + base) = c;
    }
}

// ---------------------------------------------------------------------------
// softmax in-place over last dim (1024). One block per row.
// ---------------------------------------------------------------------------
__global__ void softmax_kernel(float* __restrict__ attn) {
    size_t row = blockIdx.x;
    float* r = attn + row * Tq;
    int tid = threadIdx.x;
    int lane = tid & 31, wid = tid >> 5;
    __shared__ float sred[8];

    float v[4];
    float mx = -1e30f;
#pragma unroll
    for (int i = 0; i < 4; i++) { v[i] = r[tid + i * 256]; mx = fmaxf(mx, v[i]); }
#pragma unroll
    for (int o = 16; o > 0; o >>= 1) mx = fmaxf(mx, __shfl_down_sync(0xffffffffu, mx, o));
    if (lane == 0) sred[wid] = mx;
    __syncthreads();
    if (wid == 0) {
        mx = (lane < 8) ? sred[lane] : -1e30f;
#pragma unroll
        for (int o = 4; o > 0; o >>= 1) mx = fmaxf(mx, __shfl_down_sync(0xffffffffu, mx, o));
        if (lane == 0) sred[0] = mx;
    }
    __syncthreads();
    mx = sred[0];
    __syncthreads();

    float s = 0.f;
#pragma unroll
    for (int i = 0; i < 4; i++) { v[i] = __expf(v[i] - mx); s += v[i]; }
#pragma unroll
    for (int o = 16; o > 0; o >>= 1) s += __shfl_down_sync(0xffffffffu, s, o);
    if (lane == 0) sred[wid] = s;
    __syncthreads();
    if (wid == 0) {
        s = (lane < 8) ? sred[lane] : 0.f;
#pragma unroll
        for (int o = 4; o > 0; o >>= 1) s += __shfl_down_sync(0xffffffffu, s, o);
        if (lane == 0) sred[0] = s;
    }
    __syncthreads();
    float inv = 1.0f / sred[0];
#pragma unroll
    for (int i = 0; i < 4; i++) r[tid + i * 256] = v[i] * inv;
}

// ---------------------------------------------------------------------------
// attn @ v : ctx[b,t,h,:] = sum_s attn[bh][t][s] * v[b,s,h,:]
// ---------------------------------------------------------------------------
__global__ __launch_bounds__(256)
void av_kernel(const float* __restrict__ attn, const float* __restrict__ v,
               float* __restrict__ ctx) {
    int bh = blockIdx.y;
    int b = bh >> 4, h = bh & 15;
    const float* A = attn + (size_t)bh * Tq * Tq;
    const float* V = v   + (size_t)b * Tq * Dq + h * DHq;
    float* C       = ctx + (size_t)b * Tq * Dq + h * DHq;
    int t0 = blockIdx.x * 64;

    __shared__ float As[16][65];
    __shared__ float Vs[16][64];

    int tid = threadIdx.x;
    int tx = tid & 15, ty = tid >> 4;
    int ar = tid >> 2;
    int ac = (tid & 3) * 4;
    int vr = tid >> 4;
    int vc = (tid & 15) * 4;

    float acc[4][4] = {};
    for (int s0 = 0; s0 < Tq; s0 += 16) {
        float4 av = *(const float4*)(A + (size_t)(t0 + ar) * Tq + s0 + ac);
        As[ac + 0][ar] = av.x; As[ac + 1][ar] = av.y;
        As[ac + 2][ar] = av.z; As[ac + 3][ar] = av.w;
        float4 vv = *(const float4*)(V + (size_t)(s0 + vr) * Dq + vc);
        *(float4*)&Vs[vr][vc] = vv;
        __syncthreads();
#pragma unroll
        for (int kk = 0; kk < 16; kk++) {
            float a[4], bv[4];
#pragma unroll
            for (int i = 0; i < 4; i++) a[i]  = As[kk][ty * 4 + i];
#pragma unroll
            for (int j = 0; j < 4; j++) bv[j] = Vs[kk][tx * 4 + j];
#pragma unroll
            for (int i = 0; i < 4; i++)
#pragma unroll
                for (int j = 0; j < 4; j++)
                    acc[i][j] += a[i] * bv[j];
        }
        __syncthreads();
    }
#pragma unroll
    for (int i = 0; i < 4; i++) {
        size_t base = (size_t)(t0 + ty * 4 + i) * Dq + tx * 4;
        float4 c = {acc[i][0], acc[i][1], acc[i][2], acc[i][3]};
        *(float4*)(C + base) = c;
    }
}

// ---------------------------------------------------------------------------
extern "C" void kernel_launch(void* const* d_in, const int* in_sizes, int n_in,
                              void* d_out, int out_size) {
    const float* x     = (const float*)d_in[0];
    const float* sp    = (const float*)d_in[1];
    const float* ed    = (const float*)d_in[2];
    const float* ln1_g = (const float*)d_in[3];
    const float* ln1_b = (const float*)d_in[4];
    const float* Wq    = (const float*)d_in[5];
    const float* bq    = (const float*)d_in[6];
    const float* Wk    = (const float*)d_in[7];
    const float* bk    = (const float*)d_in[8];
    const float* Wv    = (const float*)d_in[9];
    const float* bv    = (const float*)d_in[10];
    const float* Wo    = (const float*)d_in[11];
    const float* bo    = (const float*)d_in[12];
    const float* ln2_g = (const float*)d_in[13];
    const float* ln2_b = (const float*)d_in[14];
    const float* W1    = (const float*)d_in[15];
    const float* b1    = (const float*)d_in[16];
    const float* W2    = (const float*)d_in[17];
    const float* b2    = (const float*)d_in[18];
    const float* lnb_g = (const float*)d_in[19];
    const float* lnb_b = (const float*)d_in[20];

    float* out_x = (float*)d_out;
    float* attn  = out_x + (size_t)XSZ;

    float *xn, *q, *k, *v, *ctx, *t1, *x2, *hb, *t2;
    cudaGetSymbolAddress((void**)&xn,  g_xn);
    cudaGetSymbolAddress((void**)&q,   g_q);
    cudaGetSymbolAddress((void**)&k,   g_k);
    cudaGetSymbolAddress((void**)&v,   g_v);
    cudaGetSymbolAddress((void**)&ctx, g_ctx);
    cudaGetSymbolAddress((void**)&t1,  g_t1);
    cudaGetSymbolAddress((void**)&x2,  g_x2);
    cudaGetSymbolAddress((void**)&hb,  g_h);
    cudaGetSymbolAddress((void**)&t2,  g_t2);

    // 1) ln1
    ln_kernel<<<Mq, 256>>>(x, nullptr, ln1_g, ln1_b, xn);

    // 2) Q/K/V projections on tensor pipe (K fuses +spatial+edge -> kb)
    gemm_mma<<<dim3(Dq / 128, Mq / 128), 256>>>(xn, Wq, bq, q, Dq, Dq, nullptr, nullptr, 0);
    gemm_mma<<<dim3(Dq / 128, Mq / 128), 256>>>(xn, Wk, bk, k, Dq, Dq, sp, ed, 0);
    gemm_mma<<<dim3(Dq / 128, Mq / 128), 256>>>(xn, Wv, bv, v, Dq, Dq, nullptr, nullptr, 0);

    // 3) attention scores -> softmax (in-place in d_out) -> attn @ v
    scores_kernel<<<dim3(16, 16, Bq * Hq), 256>>>(q, k, attn);
    softmax_kernel<<<Bq * Hq * Tq, 256>>>(attn);
    av_kernel<<<dim3(16, Bq * Hq), 256>>>(attn, v, ctx);

    // 4) output projection + residual + ln2
    gemm_mma<<<dim3(Dq / 128, Mq / 128), 256>>>(ctx, Wo, bo, t1, Dq, Dq, nullptr, nullptr, 0);
    ln_kernel<<<Mq, 256>>>(t1, xn, ln2_g, ln2_b, x2);

    // 5) FFN + residual + final ln -> d_out
    gemm_mma<<<dim3(Fq / 128, Mq / 128), 256>>>(x2, W1, b1, hb, Dq, Fq, nullptr, nullptr, 1);
    gemm_mma<<<dim3(Dq / 128, Mq / 128), 256>>>(hb, W2, b2, t2, Fq, Dq, nullptr, nullptr, 0);
    ln_kernel<<<Mq, 256>>>(t2, x2, lnb_g, lnb_b, out_x);
}

// round 12
// speedup vs baseline: 2.3926x; 1.2702x over previous
#include <cuda_runtime.h>
#include <cstdint>

// ---------------------------------------------------------------------------
// GraphFormer encoder layer. mma.sync tf32 everywhere (cvt.rna operands).
// B=4, T=1024, D=1024, H=16, DH=64, F=4096.  M = B*T = 4096.
// Output: [ x (4M floats) | attn (64M floats, (B,H,T,S)) ]
// ---------------------------------------------------------------------------

#define Bq 4
#define Tq 1024
#define Dq 1024
#define Hq 16
#define DHq 64
#define Fq 4096
#define Mq (Bq*Tq)              // 4096
#define XSZ (Mq*Dq)             // 4194304

// Scratch (static device globals -- allocation is forbidden)
__device__ float g_xn [XSZ];    // ln1 output (= residual)
__device__ float g_q  [XSZ];
__device__ float g_k  [XSZ];    // kb = k + spatial + edge (fused)
__device__ float g_v  [XSZ];
__device__ float g_ctx[XSZ];
__device__ float g_t1 [XSZ];    // ctx @ Wo + bo
__device__ float g_x2 [XSZ];    // ln2 output
__device__ float g_h  [Mq*Fq];  // FFN hidden (gelu)
__device__ float g_t2 [XSZ];    // h @ W2 + b2

__device__ __forceinline__ float gelu_tanh(float x) {
    float x3 = x * x * x;
    return 0.5f * x * (1.0f + tanhf(0.7978845608028654f * (x + 0.044715f * x3)));
}

__device__ __forceinline__ uint32_t smem_u32(const void* p) {
    uint32_t a;
    asm("{ .reg .u64 t; cvta.to.shared.u64 t, %1; cvt.u32.u64 %0, t; }"
        : "=r"(a) : "l"(p));
    return a;
}
__device__ __forceinline__ void cp16(uint32_t dst, const void* src) {
    asm volatile("cp.async.cg.shared.global [%0], [%1], 16;" :: "r"(dst), "l"(src));
}
__device__ __forceinline__ void cp_commit() {
    asm volatile("cp.async.commit_group;" ::: "memory");
}
__device__ __forceinline__ void cp_wait0() {
    asm volatile("cp.async.wait_group 0;" ::: "memory");
}
// round-to-nearest tf32 conversion. RZ truncation (raw bits) is BIASED toward
// zero and accumulates linearly over K-sums -> attn rel_err 2.2e-3 (measured
// R10). RNA is unbiased -> random accumulation -> ~4e-4.
__device__ __forceinline__ uint32_t RB(float v) {
    uint32_t t;
    asm("cvt.rna.tf32.f32 %0, %1;" : "=r"(t) : "f"(v));
    return t;
}

__device__ __forceinline__ void mma_tf32(float& c0, float& c1, float& c2, float& c3,
                                         uint32_t a0, uint32_t a1, uint32_t a2, uint32_t a3,
                                         uint32_t b0, uint32_t b1) {
    asm volatile("mma.sync.aligned.m16n8k8.row.col.f32.tf32.tf32.f32 "
                 "{%0,%1,%2,%3}, {%4,%5,%6,%7}, {%8,%9}, {%0,%1,%2,%3};"
                 : "+f"(c0), "+f"(c1), "+f"(c2), "+f"(c3)
                 : "r"(a0), "r"(a1), "r"(a2), "r"(a3), "r"(b0), "r"(b1));
}

// ---------------------------------------------------------------------------
// mma.sync tf32 GEMM: C[M,N] = A[M,K] @ Bm[K,N] + bias (+e1+e2 | gelu)
// 128x128 tile, BK=16, 256 thr = 8 warps (2x4), warp tile 64x32.
// ---------------------------------------------------------------------------
#define ASTR 20
#define BSTR 136

__global__ __launch_bounds__(256)
void gemm_mma(const float* __restrict__ A, const float* __restrict__ Bm,
              const float* __restrict__ bias, float* __restrict__ C,
              int K, int N,
              const float* __restrict__ e1, const float* __restrict__ e2, int act) {
    __shared__ __align__(16) float As[2][128 * ASTR];
    __shared__ __align__(16) float Bs[2][16 * BSTR];

    const int tid = threadIdx.x;
    const int wid = tid >> 5, lane = tid & 31;
    const int g = lane >> 2, tig = lane & 3;
    const int wm = (wid >> 2) * 64;
    const int wn = (wid & 3) * 32;
    const int bm = blockIdx.y * 128, bn = blockIdx.x * 128;

    const int arow = tid >> 1, acol = (tid & 1) * 8;
    const int brow = tid >> 4, bcol = (tid & 15) * 8;
    const float* Agp = A + (size_t)(bm + arow) * K + acol;
    const float* Bgp = Bm + (size_t)brow * N + bn + bcol;

    const uint32_t sA = smem_u32(As), sB = smem_u32(Bs);
    const uint32_t aDst = sA + (arow * ASTR + acol) * 4;
    const uint32_t bDst = sB + (brow * BSTR + bcol) * 4;

    float acc[4][4][4] = {};
    const int NIT = K >> 4;

    cp16(aDst, Agp);           cp16(aDst + 16, Agp + 4);
    cp16(bDst, Bgp);           cp16(bDst + 16, Bgp + 4);
    cp_commit();

    for (int it = 0; it < NIT; it++) {
        const int cur = it & 1;
        cp_wait0();
        __syncthreads();
        if (it + 1 < NIT) {
            const int nxt = 1 - cur;
            const float* ag = Agp + (size_t)(it + 1) * 16;
            const float* bg = Bgp + (size_t)(it + 1) * 16 * N;
            const uint32_t ad = aDst + nxt * (128 * ASTR * 4);
            const uint32_t bd = bDst + nxt * (16 * BSTR * 4);
            cp16(ad, ag);       cp16(ad + 16, ag + 4);
            cp16(bd, bg);       cp16(bd + 16, bg + 4);
            cp_commit();
        }

        const float* as = As[cur];
        const float* bs = Bs[cur];
#pragma unroll
        for (int kg = 0; kg < 2; kg++) {
            const int k8 = kg * 8;
            uint32_t af[4][4], bf[4][2];
#pragma unroll
            for (int i = 0; i < 4; i++) {
                const float* ar = as + (wm + i * 16 + g) * ASTR + k8 + tig;
                af[i][0] = RB(ar[0]);
                af[i][1] = RB(ar[8 * ASTR]);
                af[i][2] = RB(ar[4]);
                af[i][3] = RB(ar[8 * ASTR + 4]);
            }
#pragma unroll
            for (int j = 0; j < 4; j++) {
                const float* br = bs + (k8 + tig) * BSTR + wn + j * 8 + g;
                bf[j][0] = RB(br[0]);
                bf[j][1] = RB(br[4 * BSTR]);
            }
#pragma unroll
            for (int i = 0; i < 4; i++)
#pragma unroll
                for (int j = 0; j < 4; j++)
                    mma_tf32(acc[i][j][0], acc[i][j][1], acc[i][j][2], acc[i][j][3],
                             af[i][0], af[i][1], af[i][2], af[i][3],
                             bf[j][0], bf[j][1]);
        }
        __syncthreads();
    }

#pragma unroll
    for (int i = 0; i < 4; i++) {
#pragma unroll
        for (int j = 0; j < 4; j++) {
            const int col = bn + wn + j * 8 + 2 * tig;
            const int r0 = bm + wm + i * 16 + g;
#pragma unroll
            for (int h = 0; h < 2; h++) {
                const int row = r0 + h * 8;
                const size_t off = (size_t)row * N + col;
                float2 o;
                o.x = acc[i][j][h * 2 + 0];
                o.y = acc[i][j][h * 2 + 1];
                float2 bb = *(const float2*)(bias + col);
                o.x += bb.x; o.y += bb.y;
                if (e1) {
                    float2 a1 = *(const float2*)(e1 + off);
                    float2 a2 = *(const float2*)(e2 + off);
                    o.x += a1.x + a2.x; o.y += a1.y + a2.y;
                }
                if (act) { o.x = gelu_tanh(o.x); o.y = gelu_tanh(o.y); }
                *(float2*)(C + off) = o;
            }
        }
    }
}

// ---------------------------------------------------------------------------
// scores via mma: S[bh][t][s] = 0.125 * sum_d Q[t,d] * KB[s,d]   (NT GEMM)
// CTA tile 128t x 128s, K=64 in 4 chunks of 16. Both operands [row][k] smem.
// grid (8 s-tiles, 8 t-tiles, 64 bh), 256 thr.
// ---------------------------------------------------------------------------
#define SSTR 20

__global__ __launch_bounds__(256)
void scores_mma(const float* __restrict__ q, const float* __restrict__ kb,
                float* __restrict__ attn) {
    __shared__ __align__(16) float Qs[2][128 * SSTR];
    __shared__ __align__(16) float Ks[2][128 * SSTR];

    const int bh = blockIdx.z;
    const int b = bh >> 4, h = bh & 15;
    const float* Qg  = q  + (size_t)b * Tq * Dq + h * DHq;
    const float* KBg = kb + (size_t)b * Tq * Dq + h * DHq;
    float* S = attn + (size_t)bh * Tq * Tq;

    const int t0 = blockIdx.y * 128, s0 = blockIdx.x * 128;

    const int tid = threadIdx.x;
    const int wid = tid >> 5, lane = tid & 31;
    const int g = lane >> 2, tig = lane & 3;
    const int wm = (wid >> 2) * 64;
    const int wn = (wid & 3) * 32;

    const int arow = tid >> 1, acol = (tid & 1) * 8;
    const float* Agp = Qg  + (size_t)(t0 + arow) * Dq + acol;
    const float* Bgp = KBg + (size_t)(s0 + arow) * Dq + acol;

    const uint32_t sQ = smem_u32(Qs), sK = smem_u32(Ks);
    const uint32_t aDst = sQ + (arow * SSTR + acol) * 4;
    const uint32_t bDst = sK + (arow * SSTR + acol) * 4;

    float acc[4][4][4] = {};

    cp16(aDst, Agp);           cp16(aDst + 16, Agp + 4);
    cp16(bDst, Bgp);           cp16(bDst + 16, Bgp + 4);
    cp_commit();

#pragma unroll
    for (int it = 0; it < 4; it++) {
        const int cur = it & 1;
        cp_wait0();
        __syncthreads();
        if (it + 1 < 4) {
            const int nxt = 1 - cur;
            const float* ag = Agp + (it + 1) * 16;
            const float* bg = Bgp + (it + 1) * 16;
            const uint32_t ad = aDst + nxt * (128 * SSTR * 4);
            const uint32_t bd = bDst + nxt * (128 * SSTR * 4);
            cp16(ad, ag);       cp16(ad + 16, ag + 4);
            cp16(bd, bg);       cp16(bd + 16, bg + 4);
            cp_commit();
        }

        const float* as = Qs[cur];
        const float* bs = Ks[cur];
#pragma unroll
        for (int kg = 0; kg < 2; kg++) {
            const int k8 = kg * 8;
            uint32_t af[4][4], bf[4][2];
#pragma unroll
            for (int i = 0; i < 4; i++) {
                const float* ar = as + (wm + i * 16 + g) * SSTR + k8 + tig;
                af[i][0] = RB(ar[0]);
                af[i][1] = RB(ar[8 * SSTR]);
                af[i][2] = RB(ar[4]);
                af[i][3] = RB(ar[8 * SSTR + 4]);
            }
#pragma unroll
            for (int j = 0; j < 4; j++) {
                // [n][k] layout: b0 = B[k=tig][n], b1 = B[k=tig+4][n]
                const float* br = bs + (wn + j * 8 + g) * SSTR + k8 + tig;
                bf[j][0] = RB(br[0]);
                bf[j][1] = RB(br[4]);
            }
#pragma unroll
            for (int i = 0; i < 4; i++)
#pragma unroll
                for (int j = 0; j < 4; j++)
                    mma_tf32(acc[i][j][0], acc[i][j][1], acc[i][j][2], acc[i][j][3],
                             af[i][0], af[i][1], af[i][2], af[i][3],
                             bf[j][0], bf[j][1]);
        }
        __syncthreads();
    }

#pragma unroll
    for (int i = 0; i < 4; i++) {
#pragma unroll
        for (int j = 0; j < 4; j++) {
            const int col = s0 + wn + j * 8 + 2 * tig;
            const int r0 = t0 + wm + i * 16 + g;
#pragma unroll
            for (int h2 = 0; h2 < 2; h2++) {
                const int row = r0 + h2 * 8;
                float2 o;
                o.x = acc[i][j][h2 * 2 + 0] * 0.125f;
                o.y = acc[i][j][h2 * 2 + 1] * 0.125f;
                *(float2*)(S + (size_t)row * Tq + col) = o;
            }
        }
    }
}

// ---------------------------------------------------------------------------
// av via mma: ctx[t, dh] = sum_s attn[bh][t][s] * V[s, dh]    (NN GEMM)
// CTA tile 128t x 64dh, K=1024 in chunks of 16. grid (8 t-tiles, 64 bh).
// 8 warps (4x2), warp tile 32x32.
// ---------------------------------------------------------------------------
#define VSTR 72

__global__ __launch_bounds__(256)
void av_mma(const float* __restrict__ attn, const float* __restrict__ v,
            float* __restrict__ ctx) {
    __shared__ __align__(16) float As[2][128 * ASTR];
    __shared__ __align__(16) float Vs[2][16 * VSTR];

    const int bh = blockIdx.y;
    const int b = bh >> 4, h = bh & 15;
    const float* Ab = attn + (size_t)bh * Tq * Tq;
    const float* Vb = v   + (size_t)b * Tq * Dq + h * DHq;
    float* Cb       = ctx + (size_t)b * Tq * Dq + h * DHq;
    const int t0 = blockIdx.x * 128;

    const int tid = threadIdx.x;
    const int wid = tid >> 5, lane = tid & 31;
    const int g = lane >> 2, tig = lane & 3;
    const int wm = (wid >> 1) * 32;
    const int wn = (wid & 1) * 32;

    const int arow = tid >> 1, acol = (tid & 1) * 8;   // A: 128 x 16
    const int brow = tid >> 4, bcol = (tid & 15) * 4;  // V: 16 x 64
    const float* Agp = Ab + (size_t)(t0 + arow) * Tq + acol;
    const float* Bgp = Vb + (size_t)brow * Dq + bcol;

    const uint32_t sA = smem_u32(As), sV = smem_u32(Vs);
    const uint32_t aDst = sA + (arow * ASTR + acol) * 4;
    const uint32_t bDst = sV + (brow * VSTR + bcol) * 4;

    float acc[2][4][4] = {};
    const int NIT = Tq >> 4;   // 64

    cp16(aDst, Agp);           cp16(aDst + 16, Agp + 4);
    cp16(bDst, Bgp);
    cp_commit();

    for (int it = 0; it < NIT; it++) {
        const int cur = it & 1;
        cp_wait0();
        __syncthreads();
        if (it + 1 < NIT) {
            const int nxt = 1 - cur;
            const float* ag = Agp + (size_t)(it + 1) * 16;
            const float* bg = Bgp + (size_t)(it + 1) * 16 * Dq;
            const uint32_t ad = aDst + nxt * (128 * ASTR * 4);
            const uint32_t bd = bDst + nxt * (16 * VSTR * 4);
            cp16(ad, ag);       cp16(ad + 16, ag + 4);
            cp16(bd, bg);
            cp_commit();
        }

        const float* as = As[cur];
        const float* bs = Vs[cur];
#pragma unroll
        for (int kg = 0; kg < 2; kg++) {
            const int k8 = kg * 8;
            uint32_t af[2][4], bf[4][2];
#pragma unroll
            for (int i = 0; i < 2; i++) {
                const float* ar = as + (wm + i * 16 + g) * ASTR + k8 + tig;
                af[i][0] = RB(ar[0]);
                af[i][1] = RB(ar[8 * ASTR]);
                af[i][2] = RB(ar[4]);
                af[i][3] = RB(ar[8 * ASTR + 4]);
            }
#pragma unroll
            for (int j = 0; j < 4; j++) {
                const float* br = bs + (k8 + tig) * VSTR + wn + j * 8 + g;
                bf[j][0] = RB(br[0]);
                bf[j][1] = RB(br[4 * VSTR]);
            }
#pragma unroll
            for (int i = 0; i < 2; i++)
#pragma unroll
                for (int j = 0; j < 4; j++)
                    mma_tf32(acc[i][j][0], acc[i][j][1], acc[i][j][2], acc[i][j][3],
                             af[i][0], af[i][1], af[i][2], af[i][3],
                             bf[j][0], bf[j][1]);
        }
        __syncthreads();
    }

#pragma unroll
    for (int i = 0; i < 2; i++) {
#pragma unroll
        for (int j = 0; j < 4; j++) {
            const int col = wn + j * 8 + 2 * tig;
            const int r0 = t0 + wm + i * 16 + g;
#pragma unroll
            for (int h2 = 0; h2 < 2; h2++) {
                const int row = r0 + h2 * 8;
                float2 o;
                o.x = acc[i][j][h2 * 2 + 0];
                o.y = acc[i][j][h2 * 2 + 1];
                *(float2*)(Cb + (size_t)row * Dq + col) = o;
            }
        }
    }
}

// ---------------------------------------------------------------------------
// LayerNorm over D=1024, one block (256 thr) per row. Optional residual add.
// ---------------------------------------------------------------------------
__global__ void ln_kernel(const float* __restrict__ in, const float* __restrict__ res,
                          const float* __restrict__ gamma, const float* __restrict__ beta,
                          float* __restrict__ out) {
    int row = blockIdx.x;
    int tid = threadIdx.x;
    const float* ir = in + (size_t)row * Dq;
    const float* rr = res ? res + (size_t)row * Dq : nullptr;

    float vals[4];
    float s = 0.f, sq = 0.f;
#pragma unroll
    for (int i = 0; i < 4; i++) {
        int c = tid + i * 256;
        float v = ir[c];
        if (rr) v += rr[c];
        vals[i] = v;
        s += v; sq += v * v;
    }
    __shared__ float ss[8], ssq[8];
    int lane = tid & 31, wid = tid >> 5;
#pragma unroll
    for (int o = 16; o > 0; o >>= 1) {
        s  += __shfl_down_sync(0xffffffffu, s,  o);
        sq += __shfl_down_sync(0xffffffffu, sq, o);
    }
    if (lane == 0) { ss[wid] = s; ssq[wid] = sq; }
    __syncthreads();
    if (wid == 0) {
        s  = (lane < 8) ? ss[lane]  : 0.f;
        sq = (lane < 8) ? ssq[lane] : 0.f;
#pragma unroll
        for (int o = 4; o > 0; o >>= 1) {
            s  += __shfl_down_sync(0xffffffffu, s,  o);
            sq += __shfl_down_sync(0xffffffffu, sq, o);
        }
        if (lane == 0) { ss[0] = s; ssq[0] = sq; }
    }
    __syncthreads();
    float mean = ss[0] * (1.0f / Dq);
    float var  = ssq[0] * (1.0f / Dq) - mean * mean;
    float inv  = rsqrtf(var + 1e-5f);

    float* orow = out + (size_t)row * Dq;
#pragma unroll
    for (int i = 0; i < 4; i++) {
        int c = tid + i * 256;
        orow[c] = (vals[i] - mean) * inv * gamma[c] + beta[c];
    }
}

// ---------------------------------------------------------------------------
// softmax in-place over last dim (1024). One block per row.
// ---------------------------------------------------------------------------
__global__ void softmax_kernel(float* __restrict__ attn) {
    size_t row = blockIdx.x;
    float* r = attn + row * Tq;
    int tid = threadIdx.x;
    int lane = tid & 31, wid = tid >> 5;
    __shared__ float sred[8];

    float v[4];
    float mx = -1e30f;
#pragma unroll
    for (int i = 0; i < 4; i++) { v[i] = r[tid + i * 256]; mx = fmaxf(mx, v[i]); }
#pragma unroll
    for (int o = 16; o > 0; o >>= 1) mx = fmaxf(mx, __shfl_down_sync(0xffffffffu, mx, o));
    if (lane == 0) sred[wid] = mx;
    __syncthreads();
    if (wid == 0) {
        mx = (lane < 8) ? sred[lane] : -1e30f;
#pragma unroll
        for (int o = 4; o > 0; o >>= 1) mx = fmaxf(mx, __shfl_down_sync(0xffffffffu, mx, o));
        if (lane == 0) sred[0] = mx;
    }
    __syncthreads();
    mx = sred[0];
    __syncthreads();

    float s = 0.f;
#pragma unroll
    for (int i = 0; i < 4; i++) { v[i] = __expf(v[i] - mx); s += v[i]; }
#pragma unroll
    for (int o = 16; o > 0; o >>= 1) s += __shfl_down_sync(0xffffffffu, s, o);
    if (lane == 0) sred[wid] = s;
    __syncthreads();
    if (wid == 0) {
        s = (lane < 8) ? sred[lane] : 0.f;
#pragma unroll
        for (int o = 4; o > 0; o >>= 1) s += __shfl_down_sync(0xffffffffu, s, o);
        if (lane == 0) sred[0] = s;
    }
    __syncthreads();
    float inv = 1.0f / sred[0];
#pragma unroll
    for (int i = 0; i < 4; i++) r[tid + i * 256] = v[i] * inv;
}

// ---------------------------------------------------------------------------
extern "C" void kernel_launch(void* const* d_in, const int* in_sizes, int n_in,
                              void* d_out, int out_size) {
    const float* x     = (const float*)d_in[0];
    const float* sp    = (const float*)d_in[1];
    const float* ed    = (const float*)d_in[2];
    const float* ln1_g = (const float*)d_in[3];
    const float* ln1_b = (const float*)d_in[4];
    const float* Wq    = (const float*)d_in[5];
    const float* bq    = (const float*)d_in[6];
    const float* Wk    = (const float*)d_in[7];
    const float* bk    = (const float*)d_in[8];
    const float* Wv    = (const float*)d_in[9];
    const float* bv    = (const float*)d_in[10];
    const float* Wo    = (const float*)d_in[11];
    const float* bo    = (const float*)d_in[12];
    const float* ln2_g = (const float*)d_in[13];
    const float* ln2_b = (const float*)d_in[14];
    const float* W1    = (const float*)d_in[15];
    const float* b1    = (const float*)d_in[16];
    const float* W2    = (const float*)d_in[17];
    const float* b2    = (const float*)d_in[18];
    const float* lnb_g = (const float*)d_in[19];
    const float* lnb_b = (const float*)d_in[20];

    float* out_x = (float*)d_out;
    float* attn  = out_x + (size_t)XSZ;

    float *xn, *q, *k, *v, *ctx, *t1, *x2, *hb, *t2;
    cudaGetSymbolAddress((void**)&xn,  g_xn);
    cudaGetSymbolAddress((void**)&q,   g_q);
    cudaGetSymbolAddress((void**)&k,   g_k);
    cudaGetSymbolAddress((void**)&v,   g_v);
    cudaGetSymbolAddress((void**)&ctx, g_ctx);
    cudaGetSymbolAddress((void**)&t1,  g_t1);
    cudaGetSymbolAddress((void**)&x2,  g_x2);
    cudaGetSymbolAddress((void**)&hb,  g_h);
    cudaGetSymbolAddress((void**)&t2,  g_t2);

    // 1) ln1
    ln_kernel<<<Mq, 256>>>(x, nullptr, ln1_g, ln1_b, xn);

    // 2) Q/K/V projections on tensor pipe (K fuses +spatial+edge -> kb)
    gemm_mma<<<dim3(Dq / 128, Mq / 128), 256>>>(xn, Wq, bq, q, Dq, Dq, nullptr, nullptr, 0);
    gemm_mma<<<dim3(Dq / 128, Mq / 128), 256>>>(xn, Wk, bk, k, Dq, Dq, sp, ed, 0);
    gemm_mma<<<dim3(Dq / 128, Mq / 128), 256>>>(xn, Wv, bv, v, Dq, Dq, nullptr, nullptr, 0);

    // 3) attention: mma scores -> softmax (in-place in d_out) -> mma attn @ v
    scores_mma<<<dim3(8, 8, Bq * Hq), 256>>>(q, k, attn);
    softmax_kernel<<<Bq * Hq * Tq, 256>>>(attn);
    av_mma<<<dim3(8, Bq * Hq), 256>>>(attn, v, ctx);

    // 4) output projection + residual + ln2
    gemm_mma<<<dim3(Dq / 128, Mq / 128), 256>>>(ctx, Wo, bo, t1, Dq, Dq, nullptr, nullptr, 0);
    ln_kernel<<<Mq, 256>>>(t1, xn, ln2_g, ln2_b, x2);

    // 5) FFN + residual + final ln -> d_out
    gemm_mma<<<dim3(Fq / 128, Mq / 128), 256>>>(x2, W1, b1, hb, Dq, Fq, nullptr, nullptr, 1);
    gemm_mma<<<dim3(Dq / 128, Mq / 128), 256>>>(hb, W2, b2, t2, Fq, Dq, nullptr, nullptr, 0);
    ln_kernel<<<Mq, 256>>>(t2, x2, lnb_g, lnb_b, out_x);
}